// round 1
// baseline (speedup 1.0000x reference)
#include <cuda_runtime.h>
#include <math_constants.h>

#ifndef M_PI_F
#define M_PI_F 3.14159265358979323846f
#endif

#define FDIM 512
#define NOUT 100

// One warp per sample row.
// - Coalesced float4 loads of the 512-float row (4 float4 per lane).
// - pre_W (3x512 = 6KB) read via __ldg, L1-resident after first block warms it.
// - XOR-butterfly reduction -> all lanes hold d0,d1,d2.
// - Each lane redundantly simulates the 8-amplitude circuit (cheap, no sync).
// - 100 outputs written coalesced, lanes strided by 32.
__global__ __launch_bounds__(256, 8)
void qnet_fused_kernel(const float* __restrict__ X,
                       const float* __restrict__ preW,
                       const float* __restrict__ preB,
                       const float* __restrict__ qp,
                       const float* __restrict__ postW,
                       const float* __restrict__ postB,
                       float* __restrict__ out,
                       int B)
{
    const int warp = (blockIdx.x * blockDim.x + threadIdx.x) >> 5;
    const int lane = threadIdx.x & 31;
    if (warp >= B) return;

    const float4* __restrict__ xr = reinterpret_cast<const float4*>(X + (size_t)warp * FDIM);
    const float4* __restrict__ w0 = reinterpret_cast<const float4*>(preW);
    const float4* __restrict__ w1 = reinterpret_cast<const float4*>(preW + FDIM);
    const float4* __restrict__ w2 = reinterpret_cast<const float4*>(preW + 2 * FDIM);

    float d0 = 0.f, d1 = 0.f, d2 = 0.f;
    #pragma unroll
    for (int k = 0; k < 4; ++k) {
        const int i = lane + k * 32;            // 128 float4 per row
        const float4 x = xr[i];
        const float4 a = __ldg(w0 + i);
        const float4 b = __ldg(w1 + i);
        const float4 c = __ldg(w2 + i);
        d0 += x.x * a.x + x.y * a.y + x.z * a.z + x.w * a.w;
        d1 += x.x * b.x + x.y * b.y + x.z * b.z + x.w * b.w;
        d2 += x.x * c.x + x.y * c.y + x.z * c.z + x.w * c.w;
    }
    // butterfly: all lanes end up with the full sums
    #pragma unroll
    for (int off = 16; off > 0; off >>= 1) {
        d0 += __shfl_xor_sync(0xFFFFFFFFu, d0, off);
        d1 += __shfl_xor_sync(0xFFFFFFFFu, d1, off);
        d2 += __shfl_xor_sync(0xFFFFFFFFu, d2, off);
    }

    // q_in = tanh(pre_out) * pi/2
    const float t0 = tanhf(d0 + __ldg(preB + 0)) * (M_PI_F * 0.5f);
    const float t1 = tanhf(d1 + __ldg(preB + 1)) * (M_PI_F * 0.5f);
    const float t2 = tanhf(d2 + __ldg(preB + 2)) * (M_PI_F * 0.5f);

    // ---- 3-qubit real statevector, index = i0*4 + i1*2 + i2 ----
    float s[8];
    const float inv_sqrt8 = 0.3535533905932738f; // 1/sqrt(8): H layer on |000>
    #pragma unroll
    for (int i = 0; i < 8; ++i) s[i] = inv_sqrt8;

    auto ry0 = [&](float th) {
        float sn, cs; __sincosf(th * 0.5f, &sn, &cs);
        #pragma unroll
        for (int i = 0; i < 4; ++i) {
            float a = s[i], b = s[i + 4];
            s[i]     = cs * a - sn * b;
            s[i + 4] = sn * a + cs * b;
        }
    };
    auto ry1 = [&](float th) {
        float sn, cs; __sincosf(th * 0.5f, &sn, &cs);
        #pragma unroll
        for (int g = 0; g < 2; ++g) {
            #pragma unroll
            for (int i = 0; i < 2; ++i) {
                int lo = g * 4 + i;
                float a = s[lo], b = s[lo + 2];
                s[lo]     = cs * a - sn * b;
                s[lo + 2] = sn * a + cs * b;
            }
        }
    };
    auto ry2 = [&](float th) {
        float sn, cs; __sincosf(th * 0.5f, &sn, &cs);
        #pragma unroll
        for (int g = 0; g < 4; ++g) {
            int lo = g * 2;
            float a = s[lo], b = s[lo + 1];
            s[lo]     = cs * a - sn * b;
            s[lo + 1] = sn * a + cs * b;
        }
    };
    auto cnot01 = [&]() { // ctrl q0, tgt q1: where i0=1, swap i1
        float t;
        t = s[4]; s[4] = s[6]; s[6] = t;
        t = s[5]; s[5] = s[7]; s[7] = t;
    };
    auto cnot12 = [&]() { // ctrl q1, tgt q2: where i1=1, swap i2
        float t;
        t = s[2]; s[2] = s[3]; s[3] = t;
        t = s[6]; s[6] = s[7]; s[7] = t;
    };

    ry0(t0); ry1(t1); ry2(t2);

    // shared q_weights rows 1..2 (q_params[3..8]); tiny, L1-cached
    #pragma unroll
    for (int k = 0; k < 2; ++k) {
        cnot01();
        cnot12();
        ry0(__ldg(qp + 3 * (k + 1) + 0));
        ry1(__ldg(qp + 3 * (k + 1) + 1));
        ry2(__ldg(qp + 3 * (k + 1) + 2));
    }

    float p[8];
    #pragma unroll
    for (int i = 0; i < 8; ++i) p[i] = s[i] * s[i];

    const float z0 = (p[0] + p[1] + p[2] + p[3]) - (p[4] + p[5] + p[6] + p[7]);
    const float z1 = (p[0] + p[1] + p[4] + p[5]) - (p[2] + p[3] + p[6] + p[7]);
    const float z2 = (p[0] + p[2] + p[4] + p[6]) - (p[1] + p[3] + p[5] + p[7]);

    // out[row, n] = z . post_W[n, :] + post_b[n]
    float* __restrict__ orow = out + (size_t)warp * NOUT;
    #pragma unroll
    for (int n = lane; n < NOUT; n += 32) {
        const float a = __ldg(postW + n * 3 + 0);
        const float b = __ldg(postW + n * 3 + 1);
        const float c = __ldg(postW + n * 3 + 2);
        orow[n] = z0 * a + z1 * b + z2 * c + __ldg(postB + n);
    }
}

extern "C" void kernel_launch(void* const* d_in, const int* in_sizes, int n_in,
                              void* d_out, int out_size)
{
    const float* X     = (const float*)d_in[0]; // [B, 512]
    const float* preW  = (const float*)d_in[1]; // [3, 512]
    const float* preB  = (const float*)d_in[2]; // [3]
    const float* qp    = (const float*)d_in[3]; // [45]
    const float* postW = (const float*)d_in[4]; // [100, 3]
    const float* postB = (const float*)d_in[5]; // [100]
    float* out = (float*)d_out;                 // [B, 100]

    const int B = in_sizes[0] / FDIM;
    const int warps_per_block = 8;               // 256 threads
    const int blocks = (B + warps_per_block - 1) / warps_per_block;

    qnet_fused_kernel<<<blocks, 256>>>(X, preW, preB, qp, postW, postB, out, B);
}

// round 2
// speedup vs baseline: 1.1070x; 1.1070x over previous
#include <cuda_runtime.h>

#ifndef M_PI_F
#define M_PI_F 3.14159265358979323846f
#endif

#define FDIM 512
#define NOUT 100
#define RB 8   // rows per warp

// One warp per 8 sample rows.
// - pre_W (3x512) cached in registers once per warp (12 float4/lane).
// - post_W/post_b cached in registers once per warp.
// - Per row: 4 coalesced float4 loads of X, 48 fma, butterfly reduce,
//   lane (r mod 8) keeps the row's pre-activations.
// - ONE circuit pass simulates all 8 rows in parallel across lanes.
// - Output: shuffle z from lane r, coalesced 100-float row writes.
__global__ __launch_bounds__(256, 2)
void qnet_fused_kernel(const float* __restrict__ X,
                       const float* __restrict__ preW,
                       const float* __restrict__ preB,
                       const float* __restrict__ qp,
                       const float* __restrict__ postW,
                       const float* __restrict__ postB,
                       float* __restrict__ out,
                       int B)
{
    const int warp = (blockIdx.x * blockDim.x + threadIdx.x) >> 5;
    const int lane = threadIdx.x & 31;
    const int base = warp * RB;
    if (base >= B) return;
    const int rows = min(RB, B - base);

    // ---- cache pre_W rows in registers (once per warp) ----
    const float4* __restrict__ w0 = reinterpret_cast<const float4*>(preW);
    const float4* __restrict__ w1 = reinterpret_cast<const float4*>(preW + FDIM);
    const float4* __restrict__ w2 = reinterpret_cast<const float4*>(preW + 2 * FDIM);
    float4 wa[4], wb[4], wc[4];
    #pragma unroll
    for (int k = 0; k < 4; ++k) {
        const int i = lane + k * 32;
        wa[k] = __ldg(w0 + i);
        wb[k] = __ldg(w1 + i);
        wc[k] = __ldg(w2 + i);
    }

    // ---- cache post_W / post_b in registers (once per warp) ----
    float pw0[4], pw1[4], pw2[4], pbv[4];
    #pragma unroll
    for (int k = 0; k < 4; ++k) {
        const int n = lane + k * 32;
        if (n < NOUT) {
            pw0[k] = __ldg(postW + n * 3 + 0);
            pw1[k] = __ldg(postW + n * 3 + 1);
            pw2[k] = __ldg(postW + n * 3 + 2);
            pbv[k] = __ldg(postB + n);
        } else {
            pw0[k] = pw1[k] = pw2[k] = pbv[k] = 0.f;
        }
    }

    const float b0 = __ldg(preB + 0), b1 = __ldg(preB + 1), b2 = __ldg(preB + 2);

    // ---- dot products for RB rows; lane (r mod 8) keeps row r's sums ----
    const int myrow = lane & 7;
    float a0 = 0.f, a1 = 0.f, a2 = 0.f;

    const float4* __restrict__ xr = reinterpret_cast<const float4*>(X + (size_t)base * FDIM);

    float4 x[4];
    #pragma unroll
    for (int k = 0; k < 4; ++k) x[k] = xr[lane + k * 32];

    #pragma unroll
    for (int r = 0; r < RB; ++r) {
        // prefetch next row while we reduce this one
        float4 xn[4];
        if (r + 1 < rows) {
            #pragma unroll
            for (int k = 0; k < 4; ++k) xn[k] = xr[(r + 1) * 128 + lane + k * 32];
        }

        float d0 = 0.f, d1 = 0.f, d2 = 0.f;
        #pragma unroll
        for (int k = 0; k < 4; ++k) {
            const float4 xv = x[k];
            d0 += xv.x * wa[k].x + xv.y * wa[k].y + xv.z * wa[k].z + xv.w * wa[k].w;
            d1 += xv.x * wb[k].x + xv.y * wb[k].y + xv.z * wb[k].z + xv.w * wb[k].w;
            d2 += xv.x * wc[k].x + xv.y * wc[k].y + xv.z * wc[k].z + xv.w * wc[k].w;
        }
        #pragma unroll
        for (int off = 16; off > 0; off >>= 1) {
            d0 += __shfl_xor_sync(0xFFFFFFFFu, d0, off);
            d1 += __shfl_xor_sync(0xFFFFFFFFu, d1, off);
            d2 += __shfl_xor_sync(0xFFFFFFFFu, d2, off);
        }
        if (myrow == r) { a0 = d0; a1 = d1; a2 = d2; }

        #pragma unroll
        for (int k = 0; k < 4; ++k) x[k] = xn[k];
    }

    // ---- one circuit pass: lane (r mod 8) simulates row r ----
    const float t0 = tanhf(a0 + b0) * (M_PI_F * 0.5f);
    const float t1 = tanhf(a1 + b1) * (M_PI_F * 0.5f);
    const float t2 = tanhf(a2 + b2) * (M_PI_F * 0.5f);

    float s[8];
    const float inv_sqrt8 = 0.3535533905932738f;
    #pragma unroll
    for (int i = 0; i < 8; ++i) s[i] = inv_sqrt8;

    auto ry0 = [&](float th) {
        float sn, cs; __sincosf(th * 0.5f, &sn, &cs);
        #pragma unroll
        for (int i = 0; i < 4; ++i) {
            float a = s[i], bq = s[i + 4];
            s[i]     = cs * a - sn * bq;
            s[i + 4] = sn * a + cs * bq;
        }
    };
    auto ry1 = [&](float th) {
        float sn, cs; __sincosf(th * 0.5f, &sn, &cs);
        #pragma unroll
        for (int g = 0; g < 2; ++g)
            #pragma unroll
            for (int i = 0; i < 2; ++i) {
                int lo = g * 4 + i;
                float a = s[lo], bq = s[lo + 2];
                s[lo]     = cs * a - sn * bq;
                s[lo + 2] = sn * a + cs * bq;
            }
    };
    auto ry2 = [&](float th) {
        float sn, cs; __sincosf(th * 0.5f, &sn, &cs);
        #pragma unroll
        for (int g = 0; g < 4; ++g) {
            int lo = g * 2;
            float a = s[lo], bq = s[lo + 1];
            s[lo]     = cs * a - sn * bq;
            s[lo + 1] = sn * a + cs * bq;
        }
    };

    ry0(t0); ry1(t1); ry2(t2);

    #pragma unroll
    for (int k = 0; k < 2; ++k) {
        // CNOT(0,1): where i0=1 swap i1 ; CNOT(1,2): where i1=1 swap i2
        float tmp;
        tmp = s[4]; s[4] = s[6]; s[6] = tmp;
        tmp = s[5]; s[5] = s[7]; s[7] = tmp;
        tmp = s[2]; s[2] = s[3]; s[3] = tmp;
        tmp = s[6]; s[6] = s[7]; s[7] = tmp;
        ry0(__ldg(qp + 3 * (k + 1) + 0));
        ry1(__ldg(qp + 3 * (k + 1) + 1));
        ry2(__ldg(qp + 3 * (k + 1) + 2));
    }

    float p[8];
    #pragma unroll
    for (int i = 0; i < 8; ++i) p[i] = s[i] * s[i];

    const float z0 = (p[0] + p[1] + p[2] + p[3]) - (p[4] + p[5] + p[6] + p[7]);
    const float z1 = (p[0] + p[1] + p[4] + p[5]) - (p[2] + p[3] + p[6] + p[7]);
    const float z2 = (p[0] + p[2] + p[4] + p[6]) - (p[1] + p[3] + p[5] + p[7]);

    // ---- outputs: shuffle z from owner lane, coalesced row writes ----
    #pragma unroll
    for (int r = 0; r < RB; ++r) {
        if (r >= rows) break;
        const float zz0 = __shfl_sync(0xFFFFFFFFu, z0, r);
        const float zz1 = __shfl_sync(0xFFFFFFFFu, z1, r);
        const float zz2 = __shfl_sync(0xFFFFFFFFu, z2, r);
        float* __restrict__ orow = out + (size_t)(base + r) * NOUT;
        #pragma unroll
        for (int k = 0; k < 4; ++k) {
            const int n = lane + k * 32;
            if (n < NOUT)
                orow[n] = zz0 * pw0[k] + zz1 * pw1[k] + zz2 * pw2[k] + pbv[k];
        }
    }
}

extern "C" void kernel_launch(void* const* d_in, const int* in_sizes, int n_in,
                              void* d_out, int out_size)
{
    const float* X     = (const float*)d_in[0]; // [B, 512]
    const float* preW  = (const float*)d_in[1]; // [3, 512]
    const float* preB  = (const float*)d_in[2]; // [3]
    const float* qp    = (const float*)d_in[3]; // [45]
    const float* postW = (const float*)d_in[4]; // [100, 3]
    const float* postB = (const float*)d_in[5]; // [100]
    float* out = (float*)d_out;                 // [B, 100]

    const int B = in_sizes[0] / FDIM;
    const int warps = (B + RB - 1) / RB;
    const int warps_per_block = 8;               // 256 threads
    const int blocks = (warps + warps_per_block - 1) / warps_per_block;

    qnet_fused_kernel<<<blocks, 256>>>(X, preW, preB, qp, postW, postB, out, B);
}